// round 2
// baseline (speedup 1.0000x reference)
#include <cuda_runtime.h>
#include <cstdint>

// ---------------------------------------------------------------------------
// AbstractGenerativeUpsample
//   fea        [50000, 256]  f32
//   W_up       [8, 256, 256] f32
//   b_up       [256]         f32
//   W_cls      [256, 1]      f32
//   b_cls      [1]           f32
//   target_idx [200000]      int64 (or int32 if jax x64 disabled -> runtime detect)
// Output (concatenated, f32):
//   fea_pruned [400000, 256]  (102,400,000)
//   exist      [400000]       (   400,000)
//   target     [400000]       (   400,000)
// ---------------------------------------------------------------------------

#define NPAR  50000
#define CIN   256
#define COUT  256
#define FAN   8
#define NUP   (NPAR * FAN)          // 400000
#define NTGT  200000
#define FEA_ELEMS 102400000LL

// GEMM tiling
#define BM 64
#define BK 16
#define TM 4
#define TN 16
#define NT (CIN / BK)               // 16 k-tiles

// --------------------------- small helpers --------------------------------

__device__ __forceinline__ void cp_async16(void* smem_dst, const void* gmem_src,
                                           int src_bytes /*16 or 0*/) {
    unsigned sa = (unsigned)__cvta_generic_to_shared(smem_dst);
    asm volatile("cp.async.cg.shared.global [%0], [%1], 16, %2;\n"
                 :: "r"(sa), "l"(gmem_src), "r"(src_bytes));
}
__device__ __forceinline__ void cp_async_commit() {
    asm volatile("cp.async.commit_group;\n" ::: "memory");
}
template <int N>
__device__ __forceinline__ void cp_async_wait() {
    asm volatile("cp.async.wait_group %0;\n" :: "n"(N) : "memory");
}

// ------------------------- target_idx dtype detect -------------------------

__device__ int g_idx_stride;  // 2 if data is int64 (read low 32-bit words), 1 if int32

__global__ void detect_idx_kernel(const int* __restrict__ idx32) {
    if (threadIdx.x == 0 && blockIdx.x == 0) {
        // If the buffer holds int64 values in [0, 400000), every high dword is 0.
        // If it holds int32 random indices, sampled "high dwords" are mostly != 0.
        // Sample 64 pairs spread across the first 65536 elements-as-int64.
        int allzero = 1;
        #pragma unroll 1
        for (int i = 0; i < 64; i++) {
            if (idx32[2 * (i * 512) + 1] != 0) { allzero = 0; break; }
        }
        g_idx_stride = allzero ? 2 : 1;
    }
}

__global__ void zero_target_kernel(float* __restrict__ tgt) {
    for (int i = blockIdx.x * blockDim.x + threadIdx.x; i < NUP;
         i += gridDim.x * blockDim.x)
        tgt[i] = 0.0f;
}

__global__ void scatter_target_kernel(const int* __restrict__ idx32,
                                      float* __restrict__ tgt) {
    int i = blockIdx.x * blockDim.x + threadIdx.x;
    if (i < NTGT) {
        int s = g_idx_stride;
        int v = idx32[i * s];
        if (v >= 0 && v < NUP) tgt[v] = 1.0f;  // races benign: all write 1.0f
    }
}

// ------------------------------ fused GEMM ---------------------------------
// Block: 256 threads. Computes out rows (nb..nb+63)*8+k, all 256 cols.
// Epilogue fuses: +b_up, exist = row . W_cls + b_cls, keep = exist>0 | target,
// masked write of fea_pruned and write of exist.

__global__ __launch_bounds__(256, 2)
void upsample_gemm_kernel(const float* __restrict__ fea,
                          const float* __restrict__ Wup,
                          const float* __restrict__ bup,
                          const float* __restrict__ Wcls,
                          const float* __restrict__ bcls,
                          const float* __restrict__ target,
                          float* __restrict__ out_fea,
                          float* __restrict__ out_exist) {
    __shared__ float As[2][BM][BK];        // [m][c] 16B-contig per thread load
    __shared__ float Bs[2][BK][COUT];      // [c][d]
    __shared__ float sWcls[COUT];
    __shared__ float sBup[COUT];
    __shared__ float sEx[BM];
    __shared__ int   sKeep[BM];
    __shared__ float sBcls;

    const int k   = blockIdx.x;            // fanout slice 0..7 (fastest -> fea L2 reuse)
    const int nb  = blockIdx.y * BM;       // parent-row tile base
    const int tid = threadIdx.x;
    const int tn  = tid & 15;              // column-thread 0..15 (16 cols each)
    const int ty  = tid >> 4;              // row-thread 0..15 (4 rows each)

    if (tid < COUT) { sWcls[tid] = Wcls[tid]; sBup[tid] = bup[tid]; }
    if (tid == 0)   { sBcls = bcls[0]; }

    const float* Wk = Wup + (size_t)k * CIN * COUT;

    // A staging: thread -> (row a_m, 4 floats at col a_c)
    const int a_m = tid >> 2;              // 0..63
    const int a_c = (tid & 3) << 2;        // 0,4,8,12
    const int an  = nb + a_m;
    const int a_bytes = (an < NPAR) ? 16 : 0;
    const float* aptr = fea + (size_t)(an < NPAR ? an : 0) * CIN + a_c;
    // B staging: thread -> (row b_r, 16 floats at col b_c)
    const int b_r = ty;                    // 0..15
    const int b_c = tn << 4;               // 0..240
    const float* bptr = Wk + (size_t)b_r * COUT + b_c;

    float acc[TM][TN];
    #pragma unroll
    for (int i = 0; i < TM; i++)
        #pragma unroll
        for (int j = 0; j < TN; j++) acc[i][j] = 0.0f;

    // ---- prologue: stage tile 0 into buffer 0 ----
    cp_async16(&As[0][a_m][a_c], aptr, a_bytes);
    #pragma unroll
    for (int p = 0; p < 4; p++)
        cp_async16(&Bs[0][b_r][b_c + 4 * p], bptr + 4 * p, 16);
    cp_async_commit();

    // ---- main loop, double buffered ----
    for (int t = 0; t < NT; t++) {
        const int buf = t & 1;
        if (t + 1 < NT) {
            const int nbuf = (t + 1) & 1;
            cp_async16(&As[nbuf][a_m][a_c], aptr + (t + 1) * BK, a_bytes);
            const float* bp = bptr + (size_t)(t + 1) * BK * COUT;
            #pragma unroll
            for (int p = 0; p < 4; p++)
                cp_async16(&Bs[nbuf][b_r][b_c + 4 * p], bp + 4 * p, 16);
            cp_async_commit();
            cp_async_wait<1>();            // tile t complete
        } else {
            cp_async_wait<0>();
        }
        __syncthreads();

        #pragma unroll
        for (int kk = 0; kk < BK; kk += 4) {
            float ar[TM][4];
            #pragma unroll
            for (int i = 0; i < TM; i++) {
                float4 v = *reinterpret_cast<const float4*>(&As[buf][ty * TM + i][kk]);
                ar[i][0] = v.x; ar[i][1] = v.y; ar[i][2] = v.z; ar[i][3] = v.w;
            }
            #pragma unroll
            for (int q = 0; q < 4; q++) {
                float b[TN];
                #pragma unroll
                for (int p = 0; p < 4; p++) {
                    float4 v = *reinterpret_cast<const float4*>(&Bs[buf][kk + q][b_c + 4 * p]);
                    b[4 * p + 0] = v.x; b[4 * p + 1] = v.y;
                    b[4 * p + 2] = v.z; b[4 * p + 3] = v.w;
                }
                #pragma unroll
                for (int i = 0; i < TM; i++)
                    #pragma unroll
                    for (int j = 0; j < TN; j++)
                        acc[i][j] = fmaf(ar[i][q], b[j], acc[i][j]);
            }
        }
        __syncthreads();
    }

    // ---- epilogue: +b_up, exist reduction, keep, masked store ----
    float wj[TN], bj[TN];
    #pragma unroll
    for (int j = 0; j < TN; j++) { wj[j] = sWcls[b_c + j]; bj[j] = sBup[b_c + j]; }

    float part[TM];
    #pragma unroll
    for (int i = 0; i < TM; i++) {
        float s = 0.0f;
        #pragma unroll
        for (int j = 0; j < TN; j++) {
            acc[i][j] += bj[j];
            s = fmaf(acc[i][j], wj[j], s);
        }
        part[i] = s;
    }
    // reduce across the 16 column-threads (lanes 0-15 / 16-31 are separate ty groups)
    #pragma unroll
    for (int off = 8; off > 0; off >>= 1)
        #pragma unroll
        for (int i = 0; i < TM; i++)
            part[i] += __shfl_xor_sync(0xFFFFFFFFu, part[i], off);
    if (tn == 0) {
        #pragma unroll
        for (int i = 0; i < TM; i++) sEx[ty * TM + i] = part[i];
    }
    __syncthreads();

    if (tid < BM) {
        const int n = nb + tid;
        if (n < NPAR) {
            const float ev = sEx[tid] + sBcls;
            const size_t grow = (size_t)n * FAN + k;
            out_exist[grow] = ev;
            sKeep[tid] = (ev > 0.0f) || (__ldg(&target[grow]) > 0.5f);
        } else {
            sKeep[tid] = 0;
        }
    }
    __syncthreads();

    #pragma unroll
    for (int i = 0; i < TM; i++) {
        const int row = ty * TM + i;
        const int n = nb + row;
        if (n < NPAR) {
            const float keepf = sKeep[row] ? 1.0f : 0.0f;
            const size_t grow = (size_t)n * FAN + k;
            float* dst = out_fea + grow * COUT + b_c;
            #pragma unroll
            for (int p = 0; p < 4; p++) {
                float4 v;
                v.x = acc[i][4 * p + 0] * keepf;
                v.y = acc[i][4 * p + 1] * keepf;
                v.z = acc[i][4 * p + 2] * keepf;
                v.w = acc[i][4 * p + 3] * keepf;
                *reinterpret_cast<float4*>(dst + 4 * p) = v;
            }
        }
    }
}

// ------------------------------- launch ------------------------------------

extern "C" void kernel_launch(void* const* d_in, const int* in_sizes, int n_in,
                              void* d_out, int out_size) {
    const float* fea  = (const float*)d_in[0];
    const float* Wup  = (const float*)d_in[1];
    const float* bup  = (const float*)d_in[2];
    const float* Wcls = (const float*)d_in[3];
    const float* bcls = (const float*)d_in[4];
    const int*   idx  = (const int*)d_in[5];   // int32 view; stride detected on device

    float* out       = (float*)d_out;
    float* out_fea   = out;                       // [400000, 256]
    float* out_exist = out + FEA_ELEMS;           // [400000]
    float* out_tgt   = out + FEA_ELEMS + NUP;     // [400000]

    detect_idx_kernel<<<1, 32>>>(idx);
    zero_target_kernel<<<592, 256>>>(out_tgt);
    scatter_target_kernel<<<(NTGT + 255) / 256, 256>>>(idx, out_tgt);

    dim3 grid(FAN, (NPAR + BM - 1) / BM);        // k fastest -> fea tile shared in L2
    upsample_gemm_kernel<<<grid, 256>>>(fea, Wup, bup, Wcls, bcls,
                                        out_tgt, out_fea, out_exist);
}

// round 4
// speedup vs baseline: 3.1807x; 3.1807x over previous
#include <cuda_runtime.h>
#include <cstdint>

// ---------------------------------------------------------------------------
// AbstractGenerativeUpsample — R3 resubmit: conflict-free 128x128x8 SGEMM + FFMA2
//   fea        [50000, 256]  f32
//   W_up       [8, 256, 256] f32
//   b_up       [256] f32,  W_cls [256,1] f32,  b_cls [1] f32
//   target_idx [200000] int64 (or int32; runtime-detected)
// Output (concat f32): fea_pruned[400000,256] | exist[400000] | target[400000]
//
// exist de-fused: exist[n,k] = fea[n] . (W_k @ W_cls) + (b_up.W_cls + b_cls)
// (identical math to (fea@W_k + b_up).W_cls + b_cls; associativity only)
// ---------------------------------------------------------------------------

#define NPAR  50000
#define CIN   256
#define COUT  256
#define FAN   8
#define NUP   (NPAR * FAN)          // 400000
#define NTGT  200000
#define FEA_ELEMS 102400000LL

#define BM 128
#define BN 128
#define BKT 8
#define NT (CIN / BKT)              // 32 k-tiles

// ------------------------- device scratch (no allocs) ----------------------
__device__ float         g_Wv[FAN * COUT];   // W_k @ W_cls, per slice
__device__ float         g_c0;               // b_up . W_cls + b_cls
__device__ unsigned char g_keep[NUP];
__device__ int           g_idx_stride;       // 2 = int64 payload, 1 = int32

// --------------------------- packed f32x2 helpers --------------------------
__device__ __forceinline__ unsigned long long pack2(float x, float y) {
    unsigned long long r;
    asm("mov.b64 %0, {%1, %2};" : "=l"(r) : "f"(x), "f"(y));
    return r;
}
__device__ __forceinline__ void fma2(unsigned long long& d,
                                     unsigned long long a, unsigned long long b) {
    asm("fma.rn.f32x2 %0, %1, %2, %0;" : "+l"(d) : "l"(a), "l"(b));
}
__device__ __forceinline__ float2 unpack2(unsigned long long v) {
    float2 f;
    asm("mov.b64 {%0, %1}, %2;" : "=f"(f.x), "=f"(f.y) : "l"(v));
    return f;
}

// ------------------------- target_idx dtype detect -------------------------
__global__ void detect_idx_kernel(const int* __restrict__ idx32) {
    if (threadIdx.x == 0 && blockIdx.x == 0) {
        int allzero = 1;
        #pragma unroll 1
        for (int i = 0; i < 64; i++) {
            if (idx32[2 * (i * 512) + 1] != 0) { allzero = 0; break; }
        }
        g_idx_stride = allzero ? 2 : 1;
    }
}

// ---------------------- P0: Wv[k][c] = sum_d Wk[c][d]*Wcls[d] --------------
__global__ void wv_kernel(const float* __restrict__ Wup,
                          const float* __restrict__ Wcls) {
    __shared__ float sW[COUT];
    const int tid = threadIdx.x;
    if (tid < COUT) sW[tid] = Wcls[tid];
    __syncthreads();
    const int k = blockIdx.x >> 5;
    const int c = ((blockIdx.x & 31) << 3) + (tid >> 5);
    const int lane = tid & 31;
    const float* row = Wup + ((size_t)k * COUT + c) * CIN;
    float p = 0.0f;
    #pragma unroll
    for (int j = 0; j < 8; j++) p = fmaf(row[lane + 32 * j], sW[lane + 32 * j], p);
    #pragma unroll
    for (int off = 16; off > 0; off >>= 1)
        p += __shfl_xor_sync(0xFFFFFFFFu, p, off);
    if (lane == 0) g_Wv[k * COUT + c] = p;
}

// c0 = b_up . W_cls + b_cls
__global__ void c0_kernel(const float* __restrict__ bup,
                          const float* __restrict__ Wcls,
                          const float* __restrict__ bcls) {
    const int lane = threadIdx.x;           // 32 threads
    float p = 0.0f;
    #pragma unroll
    for (int j = 0; j < 8; j++) p = fmaf(bup[lane + 32 * j], Wcls[lane + 32 * j], p);
    #pragma unroll
    for (int off = 16; off > 0; off >>= 1)
        p += __shfl_xor_sync(0xFFFFFFFFu, p, off);
    if (lane == 0) g_c0 = p + bcls[0];
}

// ------------- P1: exist[n*8+k] = fea[n].Wv[k] + c0; keep = exist>0 --------
__global__ __launch_bounds__(256)
void exist_kernel(const float* __restrict__ fea,
                  float* __restrict__ out_exist) {
    __shared__ float sWv[FAN * COUT];       // 8KB
    const int tid = threadIdx.x;
    #pragma unroll
    for (int j = 0; j < FAN * COUT / 256; j++) sWv[tid + 256 * j] = g_Wv[tid + 256 * j];
    __syncthreads();
    const int w = tid >> 5, lane = tid & 31;
    const int n = blockIdx.x * 8 + w;       // < 50000 always (6250*8)
    const float c0 = g_c0;
    float f[8];
    const float* frow = fea + (size_t)n * CIN;
    #pragma unroll
    for (int j = 0; j < 8; j++) f[j] = frow[lane + 32 * j];
    float mye = 0.0f;
    #pragma unroll
    for (int k = 0; k < FAN; k++) {
        float p = 0.0f;
        #pragma unroll
        for (int j = 0; j < 8; j++) p = fmaf(f[j], sWv[k * COUT + lane + 32 * j], p);
        #pragma unroll
        for (int off = 16; off > 0; off >>= 1)
            p += __shfl_xor_sync(0xFFFFFFFFu, p, off);
        if (lane == k) mye = p + c0;
    }
    if (lane < FAN) {
        const size_t g = (size_t)n * FAN + lane;
        out_exist[g] = mye;
        g_keep[g] = (mye > 0.0f) ? 1 : 0;
    }
}

// ----------------------------- target scatter ------------------------------
__global__ void zero_target_kernel(float* __restrict__ tgt) {
    for (int i = blockIdx.x * blockDim.x + threadIdx.x; i < NUP;
         i += gridDim.x * blockDim.x)
        tgt[i] = 0.0f;
}

__global__ void scatter_target_kernel(const int* __restrict__ idx32,
                                      float* __restrict__ tgt) {
    int i = blockIdx.x * blockDim.x + threadIdx.x;
    if (i < NTGT) {
        int s = g_idx_stride;
        int v = idx32[i * s];
        if (v >= 0 && v < NUP) { tgt[v] = 1.0f; g_keep[v] = 1; }
    }
}

// ------------------------------ main GEMM ----------------------------------
// grid (16, 391): bx -> {k = bx&7, n-tile = bx>>3}  (k,n fastest => fea L2 reuse)
// block 256 thr; per-thread 8x8 microtile via packed f32x2 FMA.
__global__ __launch_bounds__(256, 2)
void upsample_gemm_kernel(const float* __restrict__ fea,
                          const float* __restrict__ Wup,
                          const float* __restrict__ bup,
                          float* __restrict__ out_fea) {
    __shared__ float As[2][BKT][BM];        // transposed A: [k][m]
    __shared__ float Bs[2][BKT][BN];        // [k][n]
    __shared__ float sKeep[BM];
    __shared__ float sBup[BN];

    const int k  = blockIdx.x & 7;
    const int bn = (blockIdx.x >> 3) * BN;
    const int nb = blockIdx.y * BM;
    const int tid = threadIdx.x;
    const int tx = tid & 15;                // column group
    const int ty = tid >> 4;                // row group

    // ---- staging maps ----
    const int am = tid >> 1;                // 0..127
    const int ac = (tid & 1) << 2;          // 0 or 4
    const int arow = nb + am;
    const float* aptr = fea + (size_t)(arow < NPAR ? arow : 0) * CIN + ac;
    const int br = tid >> 5;                // 0..7
    const int bc = (tid & 31) << 2;         // 0..124
    const float* bptr = Wup + (size_t)k * CIN * COUT + (size_t)br * COUT + bn + bc;

    unsigned long long acc[8][4];
    #pragma unroll
    for (int i = 0; i < 8; i++)
        #pragma unroll
        for (int j = 0; j < 4; j++) acc[i][j] = 0ull;

    // ---- prologue: tile 0 ----
    {
        float4 a0 = *reinterpret_cast<const float4*>(aptr);
        float4 b0 = *reinterpret_cast<const float4*>(bptr);
        As[0][ac + 0][am] = a0.x; As[0][ac + 1][am] = a0.y;
        As[0][ac + 2][am] = a0.z; As[0][ac + 3][am] = a0.w;
        *reinterpret_cast<float4*>(&Bs[0][br][bc]) = b0;
    }
    __syncthreads();

    // ---- main loop ----
    #pragma unroll 1
    for (int t = 0; t < NT; t++) {
        const int buf = t & 1;
        float4 a1, b1;
        if (t + 1 < NT) {
            a1 = *reinterpret_cast<const float4*>(aptr + (t + 1) * BKT);
            b1 = *reinterpret_cast<const float4*>(bptr + (size_t)(t + 1) * BKT * COUT);
        }

        const float (*A)[BM] = As[buf];
        const float (*B)[BN] = Bs[buf];
        #pragma unroll
        for (int kk = 0; kk < BKT; kk++) {
            float4 aL = *reinterpret_cast<const float4*>(&A[kk][ty * 4]);
            float4 aH = *reinterpret_cast<const float4*>(&A[kk][64 + ty * 4]);
            float4 bL = *reinterpret_cast<const float4*>(&B[kk][tx * 4]);
            float4 bH = *reinterpret_cast<const float4*>(&B[kk][64 + tx * 4]);
            unsigned long long b2[4] = {
                pack2(bL.x, bL.y), pack2(bL.z, bL.w),
                pack2(bH.x, bH.y), pack2(bH.z, bH.w)
            };
            float av[8] = {aL.x, aL.y, aL.z, aL.w, aH.x, aH.y, aH.z, aH.w};
            #pragma unroll
            for (int i = 0; i < 8; i++) {
                unsigned long long a2 = pack2(av[i], av[i]);
                #pragma unroll
                for (int j = 0; j < 4; j++) fma2(acc[i][j], a2, b2[j]);
            }
        }

        if (t + 1 < NT) {
            const int nbuf = buf ^ 1;
            As[nbuf][ac + 0][am] = a1.x; As[nbuf][ac + 1][am] = a1.y;
            As[nbuf][ac + 2][am] = a1.z; As[nbuf][ac + 3][am] = a1.w;
            *reinterpret_cast<float4*>(&Bs[nbuf][br][bc]) = b1;
        }
        __syncthreads();
    }

    // ---- epilogue: +b_up, mask by keep, store ----
    if (tid < BM) {
        const int n = nb + tid;
        sKeep[tid] = (n < NPAR && g_keep[(size_t)n * FAN + k]) ? 1.0f : 0.0f;
    }
    if (tid < BN) sBup[tid] = bup[bn + tid];
    __syncthreads();

    const float bj0 = sBup[tx * 4 + 0], bj1 = sBup[tx * 4 + 1];
    const float bj2 = sBup[tx * 4 + 2], bj3 = sBup[tx * 4 + 3];
    const float bj4 = sBup[64 + tx * 4 + 0], bj5 = sBup[64 + tx * 4 + 1];
    const float bj6 = sBup[64 + tx * 4 + 2], bj7 = sBup[64 + tx * 4 + 3];

    #pragma unroll
    for (int i = 0; i < 8; i++) {
        const int row = (i < 4) ? (ty * 4 + i) : (64 + ty * 4 + i - 4);
        const int n = nb + row;
        if (n >= NPAR) continue;
        const float keepf = sKeep[row];
        float* dst = out_fea + ((size_t)n * FAN + k) * COUT + bn;
        float2 p0 = unpack2(acc[i][0]), p1 = unpack2(acc[i][1]);
        float2 p2 = unpack2(acc[i][2]), p3 = unpack2(acc[i][3]);
        float4 v0, v1;
        v0.x = (p0.x + bj0) * keepf; v0.y = (p0.y + bj1) * keepf;
        v0.z = (p1.x + bj2) * keepf; v0.w = (p1.y + bj3) * keepf;
        v1.x = (p2.x + bj4) * keepf; v1.y = (p2.y + bj5) * keepf;
        v1.z = (p3.x + bj6) * keepf; v1.w = (p3.y + bj7) * keepf;
        *reinterpret_cast<float4*>(dst + tx * 4) = v0;
        *reinterpret_cast<float4*>(dst + 64 + tx * 4) = v1;
    }
}

// ------------------------------- launch ------------------------------------
extern "C" void kernel_launch(void* const* d_in, const int* in_sizes, int n_in,
                              void* d_out, int out_size) {
    const float* fea  = (const float*)d_in[0];
    const float* Wup  = (const float*)d_in[1];
    const float* bup  = (const float*)d_in[2];
    const float* Wcls = (const float*)d_in[3];
    const float* bcls = (const float*)d_in[4];
    const int*   idx  = (const int*)d_in[5];

    float* out       = (float*)d_out;
    float* out_fea   = out;                       // [400000, 256]
    float* out_exist = out + FEA_ELEMS;           // [400000]
    float* out_tgt   = out + FEA_ELEMS + NUP;     // [400000]

    detect_idx_kernel<<<1, 32>>>(idx);
    wv_kernel<<<256, 256>>>(Wup, Wcls);
    c0_kernel<<<1, 32>>>(bup, Wcls, bcls);
    exist_kernel<<<NPAR / 8, 256>>>(fea, out_exist);
    zero_target_kernel<<<592, 256>>>(out_tgt);
    scatter_target_kernel<<<(NTGT + 255) / 256, 256>>>(idx, out_tgt);

    dim3 grid(16, (NPAR + BM - 1) / BM);          // (k,n-tile) fastest
    upsample_gemm_kernel<<<grid, 256>>>(fea, Wup, bup, out_fea);
}

// round 9
// speedup vs baseline: 4.7053x; 1.4794x over previous
#include <cuda_runtime.h>
#include <cuda_bf16.h>
#include <cstdint>

// ---------------------------------------------------------------------------
// AbstractGenerativeUpsample — R9: split-bf16 (3-MMA) GEMM via mma.sync HMMA
// (tcgen05 unavailable: harness compiles at .target sm_100, not sm_100a)
//   fea[50000,256] f32, W_up[8,256,256] f32, b_up[256], W_cls[256,1], b_cls[1]
//   target_idx[200000] int64 (or int32; runtime-detected)
// Output (concat f32): fea_pruned[400000,256] | exist[400000] | target[400000]
//
// GEMM: fea_up = fea @ W_k via Ahi*Bhi + Ahi*Blo + Alo*Bhi (bf16 split,
// fp32 accumulate; residual ~1e-5 rel). keep mask from exact fp32 de-fused
// exist path: exist[n,k] = fea[n].(W_k@W_cls) + (b_up.W_cls + b_cls).
// ---------------------------------------------------------------------------

#define NPAR  50000
#define CIN   256
#define COUT  256
#define FAN   8
#define NUP   (NPAR * FAN)          // 400000
#define NTGT  200000
#define FEA_ELEMS 102400000LL

#define BM 128
#define BN 128
#define BK 32                        // bf16 per chunk
#define NCHUNK (CIN / BK)            // 8
#define MTILES ((NPAR + BM - 1) / BM)  // 391

// Padded smem rows: 40 bf16 = 80B stride -> ldmatrix conflict-free
#define ASTR  40
#define ATILE (128 * ASTR * 2)       // 10240 B per tile
#define BUFSZ (4 * ATILE)            // Ahi|Alo|Bhi|Blo = 40960 B
#define SM_KEEP (2 * BUFSZ)          // 81920
#define SMEM_TOTAL (SM_KEEP + 512)   // 82432

// ------------------------- device scratch (no allocs) ----------------------
__device__ __align__(256) __nv_bfloat16 g_fea_hi[NPAR * CIN];
__device__ __align__(256) __nv_bfloat16 g_fea_lo[NPAR * CIN];
__device__ __align__(256) __nv_bfloat16 g_wt_hi[FAN * COUT * CIN];  // [k][n][c]
__device__ __align__(256) __nv_bfloat16 g_wt_lo[FAN * COUT * CIN];
__device__ float         g_Wv[FAN * COUT];
__device__ float         g_c0;
__device__ unsigned char g_keep[NUP];
__device__ int           g_idx_stride;

// ------------------------------ helpers ------------------------------------
__device__ __forceinline__ uint32_t smem_u32(const void* p) {
    uint32_t a;
    asm("{ .reg .u64 t; cvta.to.shared.u64 t, %1; cvt.u32.u64 %0, t; }"
        : "=r"(a) : "l"(p));
    return a;
}
__device__ __forceinline__ void cp16(uint32_t smem_dst, const void* gsrc) {
    asm volatile("cp.async.cg.shared.global [%0], [%1], 16;\n"
                 :: "r"(smem_dst), "l"(gsrc));
}
__device__ __forceinline__ void cp_commit() {
    asm volatile("cp.async.commit_group;\n" ::: "memory");
}
template <int N>
__device__ __forceinline__ void cp_wait() {
    asm volatile("cp.async.wait_group %0;\n" :: "n"(N) : "memory");
}
__device__ __forceinline__ void ldsm_x4(uint32_t* r, uint32_t addr) {
    asm volatile("ldmatrix.sync.aligned.m8n8.x4.shared.b16 {%0,%1,%2,%3}, [%4];"
                 : "=r"(r[0]), "=r"(r[1]), "=r"(r[2]), "=r"(r[3]) : "r"(addr));
}
__device__ __forceinline__ void mma_bf16(float* d, const uint32_t* a,
                                         const uint32_t* b) {
    asm volatile(
        "mma.sync.aligned.m16n8k16.row.col.f32.bf16.bf16.f32 "
        "{%0,%1,%2,%3}, {%4,%5,%6,%7}, {%8,%9}, {%0,%1,%2,%3};"
        : "+f"(d[0]), "+f"(d[1]), "+f"(d[2]), "+f"(d[3])
        : "r"(a[0]), "r"(a[1]), "r"(a[2]), "r"(a[3]), "r"(b[0]), "r"(b[1]));
}

// ------------------------- target_idx dtype detect -------------------------
__global__ void detect_idx_kernel(const int* __restrict__ idx32) {
    if (threadIdx.x == 0 && blockIdx.x == 0) {
        int allzero = 1;
        #pragma unroll 1
        for (int i = 0; i < 64; i++) {
            if (idx32[2 * (i * 512) + 1] != 0) { allzero = 0; break; }
        }
        g_idx_stride = allzero ? 2 : 1;
    }
}

// ----------------------- bf16 split conversion prepass ---------------------
__global__ void split_fea_kernel(const float* __restrict__ fea) {
    int i = (blockIdx.x * blockDim.x + threadIdx.x) * 4;
    #pragma unroll
    for (int j = 0; j < 4; j++) {
        float x = fea[i + j];
        __nv_bfloat16 hi = __float2bfloat16_rn(x);
        __nv_bfloat16 lo = __float2bfloat16_rn(x - __bfloat162float(hi));
        g_fea_hi[i + j] = hi;
        g_fea_lo[i + j] = lo;
    }
}
// Wt[k][n][c] = split(W[k][c][n])
__global__ void split_w_kernel(const float* __restrict__ Wup) {
    int i = (blockIdx.x * blockDim.x + threadIdx.x) * 4;
    #pragma unroll
    for (int j = 0; j < 4; j++) {
        int t = i + j;
        int k = t >> 16, r = t & 65535, n = r >> 8, c = r & 255;
        float x = Wup[(k << 16) + (c << 8) + n];
        __nv_bfloat16 hi = __float2bfloat16_rn(x);
        __nv_bfloat16 lo = __float2bfloat16_rn(x - __bfloat162float(hi));
        g_wt_hi[t] = hi;
        g_wt_lo[t] = lo;
    }
}

// ---------------------- Wv[k][c] = sum_d Wk[c][d]*Wcls[d] ------------------
__global__ void wv_kernel(const float* __restrict__ Wup,
                          const float* __restrict__ Wcls) {
    __shared__ float sW[COUT];
    const int tid = threadIdx.x;
    if (tid < COUT) sW[tid] = Wcls[tid];
    __syncthreads();
    const int k = blockIdx.x >> 5;
    const int c = ((blockIdx.x & 31) << 3) + (tid >> 5);
    const int lane = tid & 31;
    const float* row = Wup + ((size_t)k * COUT + c) * CIN;
    float p = 0.0f;
    #pragma unroll
    for (int j = 0; j < 8; j++) p = fmaf(row[lane + 32 * j], sW[lane + 32 * j], p);
    #pragma unroll
    for (int off = 16; off > 0; off >>= 1)
        p += __shfl_xor_sync(0xFFFFFFFFu, p, off);
    if (lane == 0) g_Wv[k * COUT + c] = p;
}

__global__ void c0_kernel(const float* __restrict__ bup,
                          const float* __restrict__ Wcls,
                          const float* __restrict__ bcls) {
    const int lane = threadIdx.x;
    float p = 0.0f;
    #pragma unroll
    for (int j = 0; j < 8; j++) p = fmaf(bup[lane + 32 * j], Wcls[lane + 32 * j], p);
    #pragma unroll
    for (int off = 16; off > 0; off >>= 1)
        p += __shfl_xor_sync(0xFFFFFFFFu, p, off);
    if (lane == 0) g_c0 = p + bcls[0];
}

// ---------------- exist[n*8+k] = fea[n].Wv[k] + c0 (exact fp32) ------------
__global__ __launch_bounds__(256)
void exist_kernel(const float* __restrict__ fea,
                  float* __restrict__ out_exist) {
    __shared__ float sWv[FAN * COUT];
    const int tid = threadIdx.x;
    #pragma unroll
    for (int j = 0; j < FAN * COUT / 256; j++) sWv[tid + 256 * j] = g_Wv[tid + 256 * j];
    __syncthreads();
    const int w = tid >> 5, lane = tid & 31;
    const int n = blockIdx.x * 8 + w;
    const float c0 = g_c0;
    float f[8];
    const float* frow = fea + (size_t)n * CIN;
    #pragma unroll
    for (int j = 0; j < 8; j++) f[j] = frow[lane + 32 * j];
    float mye = 0.0f;
    #pragma unroll
    for (int k = 0; k < FAN; k++) {
        float p = 0.0f;
        #pragma unroll
        for (int j = 0; j < 8; j++) p = fmaf(f[j], sWv[k * COUT + lane + 32 * j], p);
        #pragma unroll
        for (int off = 16; off > 0; off >>= 1)
            p += __shfl_xor_sync(0xFFFFFFFFu, p, off);
        if (lane == k) mye = p + c0;
    }
    if (lane < FAN) {
        const size_t g = (size_t)n * FAN + lane;
        out_exist[g] = mye;
        g_keep[g] = (mye > 0.0f) ? 1 : 0;
    }
}

// ----------------------------- target scatter ------------------------------
__global__ void zero_target_kernel(float* __restrict__ tgt) {
    for (int i = blockIdx.x * blockDim.x + threadIdx.x; i < NUP;
         i += gridDim.x * blockDim.x)
        tgt[i] = 0.0f;
}
__global__ void scatter_target_kernel(const int* __restrict__ idx32,
                                      float* __restrict__ tgt) {
    int i = blockIdx.x * blockDim.x + threadIdx.x;
    if (i < NTGT) {
        int s = g_idx_stride;
        int v = idx32[i * s];
        if (v >= 0 && v < NUP) { tgt[v] = 1.0f; g_keep[v] = 1; }
    }
}

// --------------------------- main HMMA GEMM --------------------------------
// grid (16, 391): bx -> {k = bx&7, ntile = bx>>3}; by = m tile. 256 threads,
// 8 warps as 4x2 -> warp tile 32x64 (2 m16-tiles x 8 n8-tiles).
__global__ __launch_bounds__(256, 1)
void upsample_hmma_kernel(const float* __restrict__ bup,
                          float* __restrict__ out_fea) {
    extern __shared__ __align__(1024) char smem[];
    const uint32_t sb = smem_u32(smem);
    const int tid  = threadIdx.x;
    const int wid  = tid >> 5;
    const int lane = tid & 31;
    const int k    = blockIdx.x & 7;
    const int bn   = (blockIdx.x >> 3) * BN;
    const int nb   = blockIdx.y * BM;

    const int warp_m = (wid >> 1) * 32;     // 0,32,64,96
    const int warp_n = (wid & 1) * 64;      // 0,64 (local)

    float* sKeep = (float*)(smem + SM_KEEP);
    if (tid < BM) {
        const int n = nb + tid;
        sKeep[tid] = (n < NPAR && g_keep[(size_t)n * FAN + k]) ? 1.0f : 0.0f;
    }

    // ---- staging map: thread -> 2 slots; slot -> (row, 16B-col) ----
    const int s0row = tid >> 2, s0c = (tid & 3);            // slots 0..255
    const int s1row = (tid + 256) >> 2, s1c = s0c;          // slots 256..511
    int an0 = nb + s0row; if (an0 >= NPAR) an0 = NPAR - 1;
    int an1 = nb + s1row; if (an1 >= NPAR) an1 = NPAR - 1;
    const size_t aoff0 = (size_t)an0 * CIN + s0c * 8;
    const size_t aoff1 = (size_t)an1 * CIN + s1c * 8;
    const size_t boff0 = ((size_t)k * COUT + bn + s0row) * CIN + s0c * 8;
    const size_t boff1 = ((size_t)k * COUT + bn + s1row) * CIN + s1c * 8;
    const uint32_t sd0 = s0row * (ASTR * 2) + s0c * 16;
    const uint32_t sd1 = s1row * (ASTR * 2) + s1c * 16;

    float acc[2][8][4];
    #pragma unroll
    for (int mt = 0; mt < 2; mt++)
        #pragma unroll
        for (int nt = 0; nt < 8; nt++)
            #pragma unroll
            for (int j = 0; j < 4; j++) acc[mt][nt][j] = 0.0f;

    // ---- prologue: stage chunk 0 into buffer 0 ----
    {
        const size_t kc = 0;
        cp16(sb + sd0,              g_fea_hi + aoff0 + kc);
        cp16(sb + sd1,              g_fea_hi + aoff1 + kc);
        cp16(sb + ATILE + sd0,      g_fea_lo + aoff0 + kc);
        cp16(sb + ATILE + sd1,      g_fea_lo + aoff1 + kc);
        cp16(sb + 2 * ATILE + sd0,  g_wt_hi + boff0 + kc);
        cp16(sb + 2 * ATILE + sd1,  g_wt_hi + boff1 + kc);
        cp16(sb + 3 * ATILE + sd0,  g_wt_lo + boff0 + kc);
        cp16(sb + 3 * ATILE + sd1,  g_wt_lo + boff1 + kc);
        cp_commit();
    }

    // ldmatrix lane address components (element units)
    const int a_row = (lane & 15);              // row within m16 tile
    const int a_kh  = ((lane >> 4) & 1) * 8;    // k half
    const int b_row = (lane & 7) + ((lane >> 4) & 1) * 8;  // row within n16 pair
    const int b_kh  = ((lane >> 3) & 1) * 8;

    #pragma unroll 1
    for (int t = 0; t < NCHUNK; t++) {
        const uint32_t base = sb + (uint32_t)(t & 1) * BUFSZ;
        if (t + 1 < NCHUNK) {
            const uint32_t nb2 = sb + (uint32_t)((t + 1) & 1) * BUFSZ;
            const size_t kc = (size_t)(t + 1) * BK;
            cp16(nb2 + sd0,             g_fea_hi + aoff0 + kc);
            cp16(nb2 + sd1,             g_fea_hi + aoff1 + kc);
            cp16(nb2 + ATILE + sd0,     g_fea_lo + aoff0 + kc);
            cp16(nb2 + ATILE + sd1,     g_fea_lo + aoff1 + kc);
            cp16(nb2 + 2 * ATILE + sd0, g_wt_hi + boff0 + kc);
            cp16(nb2 + 2 * ATILE + sd1, g_wt_hi + boff1 + kc);
            cp16(nb2 + 3 * ATILE + sd0, g_wt_lo + boff0 + kc);
            cp16(nb2 + 3 * ATILE + sd1, g_wt_lo + boff1 + kc);
            cp_commit();
            cp_wait<1>();
        } else {
            cp_wait<0>();
        }
        __syncthreads();

        #pragma unroll
        for (int kk = 0; kk < BK; kk += 16) {
            uint32_t ah[2][4], al[2][4];
            #pragma unroll
            for (int mt = 0; mt < 2; mt++) {
                const uint32_t ao =
                    ((warp_m + mt * 16 + a_row) * ASTR + kk + a_kh) * 2;
                ldsm_x4(ah[mt], base + ao);
                ldsm_x4(al[mt], base + ATILE + ao);
            }
            uint32_t bh[4][4], bl[4][4];
            #pragma unroll
            for (int p = 0; p < 4; p++) {
                const uint32_t bo =
                    ((warp_n + p * 16 + b_row) * ASTR + kk + b_kh) * 2;
                ldsm_x4(bh[p], base + 2 * ATILE + bo);
                ldsm_x4(bl[p], base + 3 * ATILE + bo);
            }
            #pragma unroll
            for (int mt = 0; mt < 2; mt++)
                #pragma unroll
                for (int nt = 0; nt < 8; nt++) {
                    const int p = nt >> 1, q = (nt & 1) * 2;
                    mma_bf16(acc[mt][nt], ah[mt], &bh[p][q]);  // hi*hi
                    mma_bf16(acc[mt][nt], ah[mt], &bl[p][q]);  // hi*lo
                    mma_bf16(acc[mt][nt], al[mt], &bh[p][q]);  // lo*hi
                }
        }
        __syncthreads();
    }

    // ---- epilogue: +b_up, mask by keep, store ----
    float2 bb[8];
    #pragma unroll
    for (int nt = 0; nt < 8; nt++)
        bb[nt] = *reinterpret_cast<const float2*>(
            bup + bn + warp_n + nt * 8 + (lane & 3) * 2);

    #pragma unroll
    for (int mt = 0; mt < 2; mt++)
        #pragma unroll
        for (int h = 0; h < 2; h++) {
            const int row = warp_m + mt * 16 + (lane >> 2) + h * 8;
            const int n = nb + row;
            if (n >= NPAR) continue;
            const float keepf = sKeep[row];
            float* dst = out_fea + ((size_t)n * FAN + k) * COUT + bn + warp_n
                       + (lane & 3) * 2;
            #pragma unroll
            for (int nt = 0; nt < 8; nt++) {
                float2 v;
                v.x = (acc[mt][nt][h * 2 + 0] + bb[nt].x) * keepf;
                v.y = (acc[mt][nt][h * 2 + 1] + bb[nt].y) * keepf;
                *reinterpret_cast<float2*>(dst + nt * 8) = v;
            }
        }
}

// ------------------------------- launch ------------------------------------
extern "C" void kernel_launch(void* const* d_in, const int* in_sizes, int n_in,
                              void* d_out, int out_size) {
    const float* fea  = (const float*)d_in[0];
    const float* Wup  = (const float*)d_in[1];
    const float* bup  = (const float*)d_in[2];
    const float* Wcls = (const float*)d_in[3];
    const float* bcls = (const float*)d_in[4];
    const int*   idx  = (const int*)d_in[5];

    float* out       = (float*)d_out;
    float* out_fea   = out;                       // [400000, 256]
    float* out_exist = out + FEA_ELEMS;           // [400000]
    float* out_tgt   = out + FEA_ELEMS + NUP;     // [400000]

    detect_idx_kernel<<<1, 32>>>(idx);
    split_fea_kernel<<<NPAR * CIN / 1024, 256>>>(fea);
    split_w_kernel<<<FAN * COUT * CIN / 1024, 256>>>(Wup);
    wv_kernel<<<256, 256>>>(Wup, Wcls);
    c0_kernel<<<1, 32>>>(bup, Wcls, bcls);
    exist_kernel<<<NPAR / 8, 256>>>(fea, out_exist);
    zero_target_kernel<<<592, 256>>>(out_tgt);
    scatter_target_kernel<<<(NTGT + 255) / 256, 256>>>(idx, out_tgt);

    cudaFuncSetAttribute(upsample_hmma_kernel,
                         cudaFuncAttributeMaxDynamicSharedMemorySize, SMEM_TOTAL);
    dim3 grid(16, MTILES);                        // (k, ntile) fastest
    upsample_hmma_kernel<<<grid, 256, SMEM_TOTAL>>>(bup, out_fea);
}

// round 10
// speedup vs baseline: 5.9299x; 1.2603x over previous
#include <cuda_runtime.h>
#include <cuda_bf16.h>
#include <cstdint>

// ---------------------------------------------------------------------------
// AbstractGenerativeUpsample — R10: split-bf16 HMMA GEMM, 2 CTAs/SM
//   fea[50000,256] f32, W_up[8,256,256] f32, b_up[256], W_cls[256,1], b_cls[1]
//   target_idx[200000] int64 (or int32; runtime-detected)
// Output (concat f32): fea_pruned[400000,256] | exist[400000] | target[400000]
//
// GEMM: fea_up = fea @ W_k via Ahi*Bhi + Ahi*Blo + Alo*Bhi (bf16 split,
// fp32 accumulate; residual ~1e-5 rel). keep mask from exact fp32 de-fused
// exist path: exist[n,k] = fea[n].(W_k@W_cls) + (b_up.W_cls + b_cls).
// 6 launches: fused_pre | split_fea | split_w | exist(+tgt zero) | scatter | gemm
// ---------------------------------------------------------------------------

#define NPAR  50000
#define CIN   256
#define COUT  256
#define FAN   8
#define NUP   (NPAR * FAN)          // 400000
#define NTGT  200000
#define FEA_ELEMS 102400000LL

#define BM 128
#define BN 128
#define BK 32                        // bf16 per chunk
#define NCHUNK (CIN / BK)            // 8
#define MTILES ((NPAR + BM - 1) / BM)  // 391

// Padded smem rows: 40 bf16 = 80B stride -> ldmatrix conflict-free
#define ASTR  40
#define ATILE (128 * ASTR * 2)       // 10240 B per tile
#define BUFSZ (4 * ATILE)            // Ahi|Alo|Bhi|Blo = 40960 B
#define SM_KEEP (2 * BUFSZ)          // 81920
#define SMEM_TOTAL (SM_KEEP + 512)   // 82432  (x2 CTAs = 164 KB <= 228 KB)

// ------------------------- device scratch (no allocs) ----------------------
__device__ __align__(256) __nv_bfloat16 g_fea_hi[NPAR * CIN];
__device__ __align__(256) __nv_bfloat16 g_fea_lo[NPAR * CIN];
__device__ __align__(256) __nv_bfloat16 g_wt_hi[FAN * COUT * CIN];  // [k][n][c]
__device__ __align__(256) __nv_bfloat16 g_wt_lo[FAN * COUT * CIN];
__device__ float         g_Wv[FAN * COUT];
__device__ float         g_c0;
__device__ unsigned char g_keep[NUP];
__device__ int           g_idx_stride;

// ------------------------------ helpers ------------------------------------
__device__ __forceinline__ uint32_t smem_u32(const void* p) {
    uint32_t a;
    asm("{ .reg .u64 t; cvta.to.shared.u64 t, %1; cvt.u32.u64 %0, t; }"
        : "=r"(a) : "l"(p));
    return a;
}
__device__ __forceinline__ void cp16(uint32_t smem_dst, const void* gsrc) {
    asm volatile("cp.async.cg.shared.global [%0], [%1], 16;\n"
                 :: "r"(smem_dst), "l"(gsrc));
}
__device__ __forceinline__ void cp_commit() {
    asm volatile("cp.async.commit_group;\n" ::: "memory");
}
template <int N>
__device__ __forceinline__ void cp_wait() {
    asm volatile("cp.async.wait_group %0;\n" :: "n"(N) : "memory");
}
__device__ __forceinline__ void ldsm_x4(uint32_t* r, uint32_t addr) {
    asm volatile("ldmatrix.sync.aligned.m8n8.x4.shared.b16 {%0,%1,%2,%3}, [%4];"
                 : "=r"(r[0]), "=r"(r[1]), "=r"(r[2]), "=r"(r[3]) : "r"(addr));
}
__device__ __forceinline__ void mma_bf16(float* d, const uint32_t* a,
                                         const uint32_t* b) {
    asm volatile(
        "mma.sync.aligned.m16n8k16.row.col.f32.bf16.bf16.f32 "
        "{%0,%1,%2,%3}, {%4,%5,%6,%7}, {%8,%9}, {%0,%1,%2,%3};"
        : "+f"(d[0]), "+f"(d[1]), "+f"(d[2]), "+f"(d[3])
        : "r"(a[0]), "r"(a[1]), "r"(a[2]), "r"(a[3]), "r"(b[0]), "r"(b[1]));
}

// ---------------- fused pre-kernel: detect | c0 | Wv ------------------------
// block 0: tid0 = idx dtype detect; warp1 = c0.  blocks 1..256: Wv.
__global__ void fused_pre_kernel(const float* __restrict__ Wup,
                                 const float* __restrict__ Wcls,
                                 const float* __restrict__ bup,
                                 const float* __restrict__ bcls,
                                 const int* __restrict__ idx32) {
    __shared__ float sW[COUT];
    const int tid = threadIdx.x;
    if (blockIdx.x == 0) {
        if (tid == 0) {
            int allzero = 1;
            #pragma unroll 1
            for (int i = 0; i < 64; i++) {
                if (idx32[2 * (i * 512) + 1] != 0) { allzero = 0; break; }
            }
            g_idx_stride = allzero ? 2 : 1;
        } else if (tid >= 32 && tid < 64) {
            const int lane = tid - 32;
            float p = 0.0f;
            #pragma unroll
            for (int j = 0; j < 8; j++)
                p = fmaf(bup[lane + 32 * j], Wcls[lane + 32 * j], p);
            #pragma unroll
            for (int off = 16; off > 0; off >>= 1)
                p += __shfl_xor_sync(0xFFFFFFFFu, p, off);
            if (lane == 0) g_c0 = p + bcls[0];
        }
        return;
    }
    const int b = blockIdx.x - 1;            // 0..255
    if (tid < COUT) sW[tid] = Wcls[tid];
    __syncthreads();
    const int k = b >> 5;
    const int c = ((b & 31) << 3) + (tid >> 5);
    const int lane = tid & 31;
    const float* row = Wup + ((size_t)k * COUT + c) * CIN;
    float p = 0.0f;
    #pragma unroll
    for (int j = 0; j < 8; j++) p = fmaf(row[lane + 32 * j], sW[lane + 32 * j], p);
    #pragma unroll
    for (int off = 16; off > 0; off >>= 1)
        p += __shfl_xor_sync(0xFFFFFFFFu, p, off);
    if (lane == 0) g_Wv[k * COUT + c] = p;
}

// ----------------------- bf16 split conversion prepass ---------------------
__global__ void split_fea_kernel(const float* __restrict__ fea) {
    int i = (blockIdx.x * blockDim.x + threadIdx.x) * 4;
    #pragma unroll
    for (int j = 0; j < 4; j++) {
        float x = fea[i + j];
        __nv_bfloat16 hi = __float2bfloat16_rn(x);
        __nv_bfloat16 lo = __float2bfloat16_rn(x - __bfloat162float(hi));
        g_fea_hi[i + j] = hi;
        g_fea_lo[i + j] = lo;
    }
}
// Wt[k][n][c] = split(W[k][c][n])
__global__ void split_w_kernel(const float* __restrict__ Wup) {
    int i = (blockIdx.x * blockDim.x + threadIdx.x) * 4;
    #pragma unroll
    for (int j = 0; j < 4; j++) {
        int t = i + j;
        int k = t >> 16, r = t & 65535, n = r >> 8, c = r & 255;
        float x = Wup[(k << 16) + (c << 8) + n];
        __nv_bfloat16 hi = __float2bfloat16_rn(x);
        __nv_bfloat16 lo = __float2bfloat16_rn(x - __bfloat162float(hi));
        g_wt_hi[t] = hi;
        g_wt_lo[t] = lo;
    }
}

// ------- exist[n*8+k] = fea[n].Wv[k] + c0 (exact fp32); zero target --------
__global__ __launch_bounds__(256)
void exist_kernel(const float* __restrict__ fea,
                  float* __restrict__ out_exist,
                  float* __restrict__ out_tgt) {
    __shared__ float sWv[FAN * COUT];
    const int tid = threadIdx.x;
    #pragma unroll
    for (int j = 0; j < FAN * COUT / 256; j++) sWv[tid + 256 * j] = g_Wv[tid + 256 * j];
    __syncthreads();
    const int w = tid >> 5, lane = tid & 31;
    const int n = blockIdx.x * 8 + w;
    const float c0 = g_c0;
    float f[8];
    const float* frow = fea + (size_t)n * CIN;
    #pragma unroll
    for (int j = 0; j < 8; j++) f[j] = frow[lane + 32 * j];
    float mye = 0.0f;
    #pragma unroll
    for (int k = 0; k < FAN; k++) {
        float p = 0.0f;
        #pragma unroll
        for (int j = 0; j < 8; j++) p = fmaf(f[j], sWv[k * COUT + lane + 32 * j], p);
        #pragma unroll
        for (int off = 16; off > 0; off >>= 1)
            p += __shfl_xor_sync(0xFFFFFFFFu, p, off);
        if (lane == k) mye = p + c0;
    }
    if (lane < FAN) {
        const size_t g = (size_t)n * FAN + lane;
        out_exist[g] = mye;
        out_tgt[g] = 0.0f;                       // zero target here (covers NUP)
        g_keep[g] = (mye > 0.0f) ? 1 : 0;
    }
}

// ----------------------------- target scatter ------------------------------
__global__ void scatter_target_kernel(const int* __restrict__ idx32,
                                      float* __restrict__ tgt) {
    int i = blockIdx.x * blockDim.x + threadIdx.x;
    if (i < NTGT) {
        int s = g_idx_stride;
        int v = idx32[i * s];
        if (v >= 0 && v < NUP) { tgt[v] = 1.0f; g_keep[v] = 1; }
    }
}

// --------------------------- main HMMA GEMM --------------------------------
// grid (16, 391): bx -> {k = bx&7, ntile = bx>>3}; by = m tile. 256 threads,
// 8 warps as 4x2 -> warp tile 32x64. B fragments loaded per n16-pair to keep
// live registers <= 128 (2 CTAs/SM).
__global__ __launch_bounds__(256, 2)
void upsample_hmma_kernel(const float* __restrict__ bup,
                          float* __restrict__ out_fea) {
    extern __shared__ __align__(1024) char smem[];
    const uint32_t sb = smem_u32(smem);
    const int tid  = threadIdx.x;
    const int wid  = tid >> 5;
    const int lane = tid & 31;
    const int k    = blockIdx.x & 7;
    const int bn   = (blockIdx.x >> 3) * BN;
    const int nb   = blockIdx.y * BM;

    const int warp_m = (wid >> 1) * 32;     // 0,32,64,96
    const int warp_n = (wid & 1) * 64;      // 0,64 (local)

    float* sKeep = (float*)(smem + SM_KEEP);
    if (tid < BM) {
        const int n = nb + tid;
        sKeep[tid] = (n < NPAR && g_keep[(size_t)n * FAN + k]) ? 1.0f : 0.0f;
    }

    // ---- staging map: thread -> 2 slots; slot -> (row, 16B-col) ----
    const int s0row = tid >> 2, s0c = (tid & 3);
    const int s1row = (tid + 256) >> 2, s1c = s0c;
    int an0 = nb + s0row; if (an0 >= NPAR) an0 = NPAR - 1;
    int an1 = nb + s1row; if (an1 >= NPAR) an1 = NPAR - 1;
    const size_t aoff0 = (size_t)an0 * CIN + s0c * 8;
    const size_t aoff1 = (size_t)an1 * CIN + s1c * 8;
    const size_t boff0 = ((size_t)k * COUT + bn + s0row) * CIN + s0c * 8;
    const size_t boff1 = ((size_t)k * COUT + bn + s1row) * CIN + s1c * 8;
    const uint32_t sd0 = s0row * (ASTR * 2) + s0c * 16;
    const uint32_t sd1 = s1row * (ASTR * 2) + s1c * 16;

    float acc[2][8][4];
    #pragma unroll
    for (int mt = 0; mt < 2; mt++)
        #pragma unroll
        for (int nt = 0; nt < 8; nt++)
            #pragma unroll
            for (int j = 0; j < 4; j++) acc[mt][nt][j] = 0.0f;

    // ---- prologue: stage chunk 0 into buffer 0 ----
    {
        cp16(sb + sd0,              g_fea_hi + aoff0);
        cp16(sb + sd1,              g_fea_hi + aoff1);
        cp16(sb + ATILE + sd0,      g_fea_lo + aoff0);
        cp16(sb + ATILE + sd1,      g_fea_lo + aoff1);
        cp16(sb + 2 * ATILE + sd0,  g_wt_hi + boff0);
        cp16(sb + 2 * ATILE + sd1,  g_wt_hi + boff1);
        cp16(sb + 3 * ATILE + sd0,  g_wt_lo + boff0);
        cp16(sb + 3 * ATILE + sd1,  g_wt_lo + boff1);
        cp_commit();
    }

    // ldmatrix lane address components (element units)
    const int a_row = (lane & 15);
    const int a_kh  = ((lane >> 4) & 1) * 8;
    const int b_row = (lane & 7) + ((lane >> 4) & 1) * 8;
    const int b_kh  = ((lane >> 3) & 1) * 8;

    #pragma unroll 1
    for (int t = 0; t < NCHUNK; t++) {
        const uint32_t base = sb + (uint32_t)(t & 1) * BUFSZ;
        if (t + 1 < NCHUNK) {
            const uint32_t nb2 = sb + (uint32_t)((t + 1) & 1) * BUFSZ;
            const size_t kc = (size_t)(t + 1) * BK;
            cp16(nb2 + sd0,             g_fea_hi + aoff0 + kc);
            cp16(nb2 + sd1,             g_fea_hi + aoff1 + kc);
            cp16(nb2 + ATILE + sd0,     g_fea_lo + aoff0 + kc);
            cp16(nb2 + ATILE + sd1,     g_fea_lo + aoff1 + kc);
            cp16(nb2 + 2 * ATILE + sd0, g_wt_hi + boff0 + kc);
            cp16(nb2 + 2 * ATILE + sd1, g_wt_hi + boff1 + kc);
            cp16(nb2 + 3 * ATILE + sd0, g_wt_lo + boff0 + kc);
            cp16(nb2 + 3 * ATILE + sd1, g_wt_lo + boff1 + kc);
            cp_commit();
            cp_wait<1>();
        } else {
            cp_wait<0>();
        }
        __syncthreads();

        #pragma unroll
        for (int kk = 0; kk < BK; kk += 16) {
            uint32_t ah[2][4], al[2][4];
            #pragma unroll
            for (int mt = 0; mt < 2; mt++) {
                const uint32_t ao =
                    ((warp_m + mt * 16 + a_row) * ASTR + kk + a_kh) * 2;
                ldsm_x4(ah[mt], base + ao);
                ldsm_x4(al[mt], base + ATILE + ao);
            }
            // B fragments per n16-pair (keeps live registers low)
            #pragma unroll
            for (int p = 0; p < 4; p++) {
                uint32_t bh[4], bl[4];
                const uint32_t bo =
                    ((warp_n + p * 16 + b_row) * ASTR + kk + b_kh) * 2;
                ldsm_x4(bh, base + 2 * ATILE + bo);
                ldsm_x4(bl, base + 3 * ATILE + bo);
                #pragma unroll
                for (int mt = 0; mt < 2; mt++) {
                    #pragma unroll
                    for (int half = 0; half < 2; half++) {
                        float* d = acc[mt][2 * p + half];
                        mma_bf16(d, ah[mt], &bh[2 * half]);   // hi*hi
                        mma_bf16(d, ah[mt], &bl[2 * half]);   // hi*lo
                        mma_bf16(d, al[mt], &bh[2 * half]);   // lo*hi
                    }
                }
            }
        }
        __syncthreads();
    }

    // ---- epilogue: +b_up, mask by keep, store ----
    float2 bb[8];
    #pragma unroll
    for (int nt = 0; nt < 8; nt++)
        bb[nt] = *reinterpret_cast<const float2*>(
            bup + bn + warp_n + nt * 8 + (lane & 3) * 2);

    #pragma unroll
    for (int mt = 0; mt < 2; mt++)
        #pragma unroll
        for (int h = 0; h < 2; h++) {
            const int row = warp_m + mt * 16 + (lane >> 2) + h * 8;
            const int n = nb + row;
            if (n >= NPAR) continue;
            const float keepf = sKeep[row];
            float* dst = out_fea + ((size_t)n * FAN + k) * COUT + bn + warp_n
                       + (lane & 3) * 2;
            #pragma unroll
            for (int nt = 0; nt < 8; nt++) {
                float2 v;
                v.x = (acc[mt][nt][h * 2 + 0] + bb[nt].x) * keepf;
                v.y = (acc[mt][nt][h * 2 + 1] + bb[nt].y) * keepf;
                *reinterpret_cast<float2*>(dst + nt * 8) = v;
            }
        }
}

// ------------------------------- launch ------------------------------------
extern "C" void kernel_launch(void* const* d_in, const int* in_sizes, int n_in,
                              void* d_out, int out_size) {
    const float* fea  = (const float*)d_in[0];
    const float* Wup  = (const float*)d_in[1];
    const float* bup  = (const float*)d_in[2];
    const float* Wcls = (const float*)d_in[3];
    const float* bcls = (const float*)d_in[4];
    const int*   idx  = (const int*)d_in[5];

    float* out       = (float*)d_out;
    float* out_fea   = out;                       // [400000, 256]
    float* out_exist = out + FEA_ELEMS;           // [400000]
    float* out_tgt   = out + FEA_ELEMS + NUP;     // [400000]

    fused_pre_kernel<<<257, 256>>>(Wup, Wcls, bup, bcls, idx);
    split_fea_kernel<<<NPAR * CIN / 1024, 256>>>(fea);
    split_w_kernel<<<FAN * COUT * CIN / 1024, 256>>>(Wup);
    exist_kernel<<<NPAR / 8, 256>>>(fea, out_exist, out_tgt);
    scatter_target_kernel<<<(NTGT + 255) / 256, 256>>>(idx, out_tgt);

    cudaFuncSetAttribute(upsample_hmma_kernel,
                         cudaFuncAttributeMaxDynamicSharedMemorySize, SMEM_TOTAL);
    dim3 grid(16, MTILES);                        // (k, ntile) fastest
    upsample_hmma_kernel<<<grid, 256, SMEM_TOTAL>>>(bup, out_fea);
}

// round 13
// speedup vs baseline: 6.1159x; 1.0314x over previous
#include <cuda_runtime.h>
#include <cuda_bf16.h>
#include <cstdint>

// ---------------------------------------------------------------------------
// AbstractGenerativeUpsample — R13 (R11 resubmit #2): split-bf16 HMMA @ occ2,
// fused prepass, GEMM at launch idx 3 (= ncu capture slot).
//   fea[50000,256] f32, W_up[8,256,256] f32, b_up[256], W_cls[256,1], b_cls[1]
//   target_idx[200000] int64 (or int32; runtime-detected)
// Output (concat f32): fea_pruned[400000,256] | exist[400000] | target[400000]
//
// 4 launches: fused_pre(detect|c0|Wv|split_w) -> exist_split(exist|keep|
// tgt-zero|fea split) -> scatter -> GEMM.
// GEMM: fea_up = fea @ W_k via Ahi*Bhi + Ahi*Blo + Alo*Bhi (bf16 split,
// fp32 accumulate; residual ~1e-5). keep from exact fp32 de-fused exist.
// ---------------------------------------------------------------------------

#define NPAR  50000
#define CIN   256
#define COUT  256
#define FAN   8
#define NUP   (NPAR * FAN)          // 400000
#define NTGT  200000
#define FEA_ELEMS 102400000LL

#define BM 128
#define BN 128
#define BK 32                        // bf16 per chunk
#define NCHUNK (CIN / BK)            // 8
#define MTILES ((NPAR + BM - 1) / BM)  // 391

// Padded smem rows: 40 bf16 = 80B stride -> ldmatrix conflict-free
#define ASTR  40
#define ATILE (128 * ASTR * 2)       // 10240 B per tile
#define BUFSZ (4 * ATILE)            // Ahi|Alo|Bhi|Blo = 40960 B
#define SM_KEEP (2 * BUFSZ)          // 81920
#define SMEM_TOTAL (SM_KEEP + 512)   // 82432  (x2 CTAs = 164 KB <= 228 KB)

// ------------------------- device scratch (no allocs) ----------------------
__device__ __align__(256) __nv_bfloat16 g_fea_hi[NPAR * CIN];
__device__ __align__(256) __nv_bfloat16 g_fea_lo[NPAR * CIN];
__device__ __align__(256) __nv_bfloat16 g_wt_hi[FAN * COUT * CIN];  // [k][n][c]
__device__ __align__(256) __nv_bfloat16 g_wt_lo[FAN * COUT * CIN];
__device__ float         g_Wv[FAN * COUT];
__device__ float         g_c0;
__device__ unsigned char g_keep[NUP];
__device__ int           g_idx_stride;

// ------------------------------ helpers ------------------------------------
__device__ __forceinline__ uint32_t smem_u32(const void* p) {
    uint32_t a;
    asm("{ .reg .u64 t; cvta.to.shared.u64 t, %1; cvt.u32.u64 %0, t; }"
        : "=r"(a) : "l"(p));
    return a;
}
__device__ __forceinline__ void cp16(uint32_t smem_dst, const void* gsrc) {
    asm volatile("cp.async.cg.shared.global [%0], [%1], 16;\n"
                 :: "r"(smem_dst), "l"(gsrc));
}
__device__ __forceinline__ void cp_commit() {
    asm volatile("cp.async.commit_group;\n" ::: "memory");
}
template <int N>
__device__ __forceinline__ void cp_wait() {
    asm volatile("cp.async.wait_group %0;\n" :: "n"(N) : "memory");
}
__device__ __forceinline__ void ldsm_x4(uint32_t* r, uint32_t addr) {
    asm volatile("ldmatrix.sync.aligned.m8n8.x4.shared.b16 {%0,%1,%2,%3}, [%4];"
                 : "=r"(r[0]), "=r"(r[1]), "=r"(r[2]), "=r"(r[3]) : "r"(addr));
}
__device__ __forceinline__ void mma_bf16(float* d, const uint32_t* a,
                                         const uint32_t* b) {
    asm volatile(
        "mma.sync.aligned.m16n8k16.row.col.f32.bf16.bf16.f32 "
        "{%0,%1,%2,%3}, {%4,%5,%6,%7}, {%8,%9}, {%0,%1,%2,%3};"
        : "+f"(d[0]), "+f"(d[1]), "+f"(d[2]), "+f"(d[3])
        : "r"(a[0]), "r"(a[1]), "r"(a[2]), "r"(a[3]), "r"(b[0]), "r"(b[1]));
}

// ------------- fused pre-kernel: detect | c0 | Wv | split_w ----------------
// block 0: tid0 detect, warp1 c0.  blocks 1..256: Wv.  blocks 257..768: split_w.
__global__ void fused_pre_kernel(const float* __restrict__ Wup,
                                 const float* __restrict__ Wcls,
                                 const float* __restrict__ bup,
                                 const float* __restrict__ bcls,
                                 const int* __restrict__ idx32) {
    __shared__ float sW[COUT];
    const int tid = threadIdx.x;
    const int bx = blockIdx.x;
    if (bx == 0) {
        if (tid == 0) {
            int allzero = 1;
            #pragma unroll 1
            for (int i = 0; i < 64; i++) {
                if (idx32[2 * (i * 512) + 1] != 0) { allzero = 0; break; }
            }
            g_idx_stride = allzero ? 2 : 1;
        } else if (tid >= 32 && tid < 64) {
            const int lane = tid - 32;
            float p = 0.0f;
            #pragma unroll
            for (int j = 0; j < 8; j++)
                p = fmaf(bup[lane + 32 * j], Wcls[lane + 32 * j], p);
            #pragma unroll
            for (int off = 16; off > 0; off >>= 1)
                p += __shfl_xor_sync(0xFFFFFFFFu, p, off);
            if (lane == 0) g_c0 = p + bcls[0];
        }
        return;
    }
    if (bx <= 256) {                         // Wv[k][c] = Wk[c][:] . Wcls
        const int b = bx - 1;
        if (tid < COUT) sW[tid] = Wcls[tid];
        __syncthreads();
        const int k = b >> 5;
        const int c = ((b & 31) << 3) + (tid >> 5);
        const int lane = tid & 31;
        const float* row = Wup + ((size_t)k * COUT + c) * CIN;
        float p = 0.0f;
        #pragma unroll
        for (int j = 0; j < 8; j++)
            p = fmaf(row[lane + 32 * j], sW[lane + 32 * j], p);
        #pragma unroll
        for (int off = 16; off > 0; off >>= 1)
            p += __shfl_xor_sync(0xFFFFFFFFu, p, off);
        if (lane == 0) g_Wv[k * COUT + c] = p;
        return;
    }
    // split_w: Wt[k][n][c] = split(W[k][c][n]); blocks 257..768 -> 512 blocks
    const int base = (bx - 257) * 1024 + tid * 4;
    #pragma unroll
    for (int j = 0; j < 4; j++) {
        int t = base + j;
        int k = t >> 16, r = t & 65535, n = r >> 8, c = r & 255;
        float x = Wup[(k << 16) + (c << 8) + n];
        __nv_bfloat16 hi = __float2bfloat16_rn(x);
        __nv_bfloat16 lo = __float2bfloat16_rn(x - __bfloat162float(hi));
        g_wt_hi[t] = hi;
        g_wt_lo[t] = lo;
    }
}

// ---- exist (+keep, +tgt zero) fused with fea hi/lo split: one fea read ----
__global__ __launch_bounds__(256)
void exist_split_kernel(const float* __restrict__ fea,
                        float* __restrict__ out_exist,
                        float* __restrict__ out_tgt) {
    __shared__ float sWv[FAN * COUT];
    const int tid = threadIdx.x;
    #pragma unroll
    for (int j = 0; j < FAN * COUT / 256; j++) sWv[tid + 256 * j] = g_Wv[tid + 256 * j];
    __syncthreads();
    const int w = tid >> 5, lane = tid & 31;
    const int n = blockIdx.x * 8 + w;
    const float c0 = g_c0;
    float f[8];
    const float* frow = fea + (size_t)n * CIN;
    #pragma unroll
    for (int j = 0; j < 8; j++) f[j] = frow[lane + 32 * j];
    // bf16 split store (hi/lo), same interleaved addressing (coalesced 64B)
    #pragma unroll
    for (int j = 0; j < 8; j++) {
        __nv_bfloat16 hi = __float2bfloat16_rn(f[j]);
        __nv_bfloat16 lo = __float2bfloat16_rn(f[j] - __bfloat162float(hi));
        g_fea_hi[(size_t)n * CIN + lane + 32 * j] = hi;
        g_fea_lo[(size_t)n * CIN + lane + 32 * j] = lo;
    }
    float mye = 0.0f;
    #pragma unroll
    for (int k = 0; k < FAN; k++) {
        float p = 0.0f;
        #pragma unroll
        for (int j = 0; j < 8; j++) p = fmaf(f[j], sWv[k * COUT + lane + 32 * j], p);
        #pragma unroll
        for (int off = 16; off > 0; off >>= 1)
            p += __shfl_xor_sync(0xFFFFFFFFu, p, off);
        if (lane == k) mye = p + c0;
    }
    if (lane < FAN) {
        const size_t g = (size_t)n * FAN + lane;
        out_exist[g] = mye;
        out_tgt[g] = 0.0f;
        g_keep[g] = (mye > 0.0f) ? 1 : 0;
    }
}

// ----------------------------- target scatter ------------------------------
__global__ void scatter_target_kernel(const int* __restrict__ idx32,
                                      float* __restrict__ tgt) {
    int i = blockIdx.x * blockDim.x + threadIdx.x;
    if (i < NTGT) {
        int s = g_idx_stride;
        int v = idx32[i * s];
        if (v >= 0 && v < NUP) { tgt[v] = 1.0f; g_keep[v] = 1; }
    }
}

// --------------------------- main HMMA GEMM --------------------------------
__global__ __launch_bounds__(256, 2)
void upsample_hmma_kernel(const float* __restrict__ bup,
                          float* __restrict__ out_fea) {
    extern __shared__ __align__(1024) char smem[];
    const uint32_t sb = smem_u32(smem);
    const int tid  = threadIdx.x;
    const int wid  = tid >> 5;
    const int lane = tid & 31;
    const int k    = blockIdx.x & 7;
    const int bn   = (blockIdx.x >> 3) * BN;
    const int nb   = blockIdx.y * BM;

    const int warp_m = (wid >> 1) * 32;
    const int warp_n = (wid & 1) * 64;

    float* sKeep = (float*)(smem + SM_KEEP);
    if (tid < BM) {
        const int n = nb + tid;
        sKeep[tid] = (n < NPAR && g_keep[(size_t)n * FAN + k]) ? 1.0f : 0.0f;
    }

    const int s0row = tid >> 2, s0c = (tid & 3);
    const int s1row = (tid + 256) >> 2, s1c = s0c;
    int an0 = nb + s0row; if (an0 >= NPAR) an0 = NPAR - 1;
    int an1 = nb + s1row; if (an1 >= NPAR) an1 = NPAR - 1;
    const size_t aoff0 = (size_t)an0 * CIN + s0c * 8;
    const size_t aoff1 = (size_t)an1 * CIN + s1c * 8;
    const size_t boff0 = ((size_t)k * COUT + bn + s0row) * CIN + s0c * 8;
    const size_t boff1 = ((size_t)k * COUT + bn + s1row) * CIN + s1c * 8;
    const uint32_t sd0 = s0row * (ASTR * 2) + s0c * 16;
    const uint32_t sd1 = s1row * (ASTR * 2) + s1c * 16;

    float acc[2][8][4];
    #pragma unroll
    for (int mt = 0; mt < 2; mt++)
        #pragma unroll
        for (int nt = 0; nt < 8; nt++)
            #pragma unroll
            for (int j = 0; j < 4; j++) acc[mt][nt][j] = 0.0f;

    {
        cp16(sb + sd0,              g_fea_hi + aoff0);
        cp16(sb + sd1,              g_fea_hi + aoff1);
        cp16(sb + ATILE + sd0,      g_fea_lo + aoff0);
        cp16(sb + ATILE + sd1,      g_fea_lo + aoff1);
        cp16(sb + 2 * ATILE + sd0,  g_wt_hi + boff0);
        cp16(sb + 2 * ATILE + sd1,  g_wt_hi + boff1);
        cp16(sb + 3 * ATILE + sd0,  g_wt_lo + boff0);
        cp16(sb + 3 * ATILE + sd1,  g_wt_lo + boff1);
        cp_commit();
    }

    const int a_row = (lane & 15);
    const int a_kh  = ((lane >> 4) & 1) * 8;
    const int b_row = (lane & 7) + ((lane >> 4) & 1) * 8;
    const int b_kh  = ((lane >> 3) & 1) * 8;

    #pragma unroll 1
    for (int t = 0; t < NCHUNK; t++) {
        const uint32_t base = sb + (uint32_t)(t & 1) * BUFSZ;
        if (t + 1 < NCHUNK) {
            const uint32_t nb2 = sb + (uint32_t)((t + 1) & 1) * BUFSZ;
            const size_t kc = (size_t)(t + 1) * BK;
            cp16(nb2 + sd0,             g_fea_hi + aoff0 + kc);
            cp16(nb2 + sd1,             g_fea_hi + aoff1 + kc);
            cp16(nb2 + ATILE + sd0,     g_fea_lo + aoff0 + kc);
            cp16(nb2 + ATILE + sd1,     g_fea_lo + aoff1 + kc);
            cp16(nb2 + 2 * ATILE + sd0, g_wt_hi + boff0 + kc);
            cp16(nb2 + 2 * ATILE + sd1, g_wt_hi + boff1 + kc);
            cp16(nb2 + 3 * ATILE + sd0, g_wt_lo + boff0 + kc);
            cp16(nb2 + 3 * ATILE + sd1, g_wt_lo + boff1 + kc);
            cp_commit();
            cp_wait<1>();
        } else {
            cp_wait<0>();
        }
        __syncthreads();

        #pragma unroll
        for (int kk = 0; kk < BK; kk += 16) {
            uint32_t ah[2][4], al[2][4];
            #pragma unroll
            for (int mt = 0; mt < 2; mt++) {
                const uint32_t ao =
                    ((warp_m + mt * 16 + a_row) * ASTR + kk + a_kh) * 2;
                ldsm_x4(ah[mt], base + ao);
                ldsm_x4(al[mt], base + ATILE + ao);
            }
            #pragma unroll
            for (int p = 0; p < 4; p++) {
                uint32_t bh[4], bl[4];
                const uint32_t bo =
                    ((warp_n + p * 16 + b_row) * ASTR + kk + b_kh) * 2;
                ldsm_x4(bh, base + 2 * ATILE + bo);
                ldsm_x4(bl, base + 3 * ATILE + bo);
                #pragma unroll
                for (int mt = 0; mt < 2; mt++) {
                    #pragma unroll
                    for (int half = 0; half < 2; half++) {
                        float* d = acc[mt][2 * p + half];
                        mma_bf16(d, ah[mt], &bh[2 * half]);
                        mma_bf16(d, ah[mt], &bl[2 * half]);
                        mma_bf16(d, al[mt], &bh[2 * half]);
                    }
                }
            }
        }
        __syncthreads();
    }

    float2 bb[8];
    #pragma unroll
    for (int nt = 0; nt < 8; nt++)
        bb[nt] = *reinterpret_cast<const float2*>(
            bup + bn + warp_n + nt * 8 + (lane & 3) * 2);

    #pragma unroll
    for (int mt = 0; mt < 2; mt++)
        #pragma unroll
        for (int h = 0; h < 2; h++) {
            const int row = warp_m + mt * 16 + (lane >> 2) + h * 8;
            const int n = nb + row;
            if (n >= NPAR) continue;
            const float keepf = sKeep[row];
            float* dst = out_fea + ((size_t)n * FAN + k) * COUT + bn + warp_n
                       + (lane & 3) * 2;
            #pragma unroll
            for (int nt = 0; nt < 8; nt++) {
                float2 v;
                v.x = (acc[mt][nt][h * 2 + 0] + bb[nt].x) * keepf;
                v.y = (acc[mt][nt][h * 2 + 1] + bb[nt].y) * keepf;
                *reinterpret_cast<float2*>(dst + nt * 8) = v;
            }
        }
}

// ------------------------------- launch ------------------------------------
extern "C" void kernel_launch(void* const* d_in, const int* in_sizes, int n_in,
                              void* d_out, int out_size) {
    const float* fea  = (const float*)d_in[0];
    const float* Wup  = (const float*)d_in[1];
    const float* bup  = (const float*)d_in[2];
    const float* Wcls = (const float*)d_in[3];
    const float* bcls = (const float*)d_in[4];
    const int*   idx  = (const int*)d_in[5];

    float* out       = (float*)d_out;
    float* out_fea   = out;                       // [400000, 256]
    float* out_exist = out + FEA_ELEMS;           // [400000]
    float* out_tgt   = out + FEA_ELEMS + NUP;     // [400000]

    fused_pre_kernel<<<769, 256>>>(Wup, Wcls, bup, bcls, idx);      // idx 0
    exist_split_kernel<<<NPAR / 8, 256>>>(fea, out_exist, out_tgt); // idx 1
    scatter_target_kernel<<<(NTGT + 255) / 256, 256>>>(idx, out_tgt); // idx 2

    cudaFuncSetAttribute(upsample_hmma_kernel,
                         cudaFuncAttributeMaxDynamicSharedMemorySize, SMEM_TOTAL);
    dim3 grid(16, MTILES);
    upsample_hmma_kernel<<<grid, 256, SMEM_TOTAL>>>(bup, out_fea);  // idx 3
}